// round 1
// baseline (speedup 1.0000x reference)
#include <cuda_runtime.h>
#include <math.h>

// ---------------- problem constants ----------------
#define BB      2
#define SS      4096
#define HID     768
#define LAYERS  4
#define HEADS   12
#define HD      64
#define WIN     128          // one-sided window
#define MROWS   (BB*SS)      // 8192 token rows

// ---------------- scratch (device globals; no allocation) ----------------
__device__ float g_h[MROWS * HID];
__device__ float g_q[MROWS * HID];
__device__ float g_k[MROWS * HID];
__device__ float g_v[MROWS * HID];
__device__ float g_a[MROWS * HID];
__device__ float g_t[MROWS * HID];
__device__ float g_f[MROWS * 4 * HID];

// ---------------- block reduction helper (768-wide rows, 256 threads) ----
__device__ __forceinline__ float block_sum(float v, float* sh) {
    __syncthreads();
    int lane = threadIdx.x & 31, w = threadIdx.x >> 5;
#pragma unroll
    for (int o = 16; o; o >>= 1) v += __shfl_xor_sync(0xffffffffu, v, o);
    if (lane == 0) sh[w] = v;
    __syncthreads();
    if (w == 0) {
        float t = (lane < 8) ? sh[lane] : 0.f;
#pragma unroll
        for (int o = 4; o; o >>= 1) t += __shfl_xor_sync(0xffffffffu, t, o);
        if (lane == 0) sh[0] = t;
    }
    __syncthreads();
    return sh[0];
}

// ---------------- embeddings + LN ----------------
__global__ __launch_bounds__(256) void embed_ln_kernel(
    const float* __restrict__ emb, const float* __restrict__ pos,
    const float* __restrict__ tok, const float* __restrict__ g,
    const float* __restrict__ b, float* __restrict__ out)
{
    __shared__ float sh[8];
    int row = blockIdx.x;               // 0..8191
    int s = row & (SS - 1);
    int tid = threadIdx.x;
    float x[3];
#pragma unroll
    for (int i = 0; i < 3; ++i) {
        int j = tid + i * 256;
        x[i] = emb[(size_t)row * HID + j] + pos[(size_t)(s + 1) * HID + j] + tok[j];
    }
    float mean = block_sum(x[0] + x[1] + x[2], sh) * (1.f / HID);
    float d2 = 0.f;
#pragma unroll
    for (int i = 0; i < 3; ++i) { float d = x[i] - mean; d2 += d * d; }
    float var = block_sum(d2, sh) * (1.f / HID);
    float rs = rsqrtf(var + 1e-12f);
#pragma unroll
    for (int i = 0; i < 3; ++i) {
        int j = tid + i * 256;
        out[(size_t)row * HID + j] = (x[i] - mean) * rs * g[j] + b[j];
    }
}

// ---------------- residual add + LN (in-place on h allowed) -------------
__global__ __launch_bounds__(256) void add_ln_kernel(
    const float* __restrict__ hin, const float* __restrict__ xin,
    const float* __restrict__ g, const float* __restrict__ b,
    float* __restrict__ out)
{
    __shared__ float sh[8];
    int row = blockIdx.x;
    int tid = threadIdx.x;
    float x[3];
#pragma unroll
    for (int i = 0; i < 3; ++i) {
        int j = tid + i * 256;
        x[i] = hin[(size_t)row * HID + j] + xin[(size_t)row * HID + j];
    }
    float mean = block_sum(x[0] + x[1] + x[2], sh) * (1.f / HID);
    float d2 = 0.f;
#pragma unroll
    for (int i = 0; i < 3; ++i) { float d = x[i] - mean; d2 += d * d; }
    float var = block_sum(d2, sh) * (1.f / HID);
    float rs = rsqrtf(var + 1e-12f);
#pragma unroll
    for (int i = 0; i < 3; ++i) {
        int j = tid + i * 256;
        out[(size_t)row * HID + j] = (x[i] - mean) * rs * g[j] + b[j];
    }
}

// ---------------- SGEMM: C = A[M,K] * B[K,N] + bias, optional GELU ------
// BM=BN=64, BK=16, 256 threads, 4x4 register tile per thread.
__global__ __launch_bounds__(256) void sgemm_kernel(
    const float* __restrict__ A, const float* __restrict__ Bw,
    const float* __restrict__ bias, float* __restrict__ C,
    int M, int N, int K, int act)
{
    __shared__ float As[16][64];
    __shared__ float Bs[16][64];
    int tid = threadIdx.x;
    int tx = tid & 15, ty = tid >> 4;
    int bn = blockIdx.x * 64, bm = blockIdx.y * 64;

    int lrowA = tid >> 2;          // 0..63
    int lk4A  = (tid & 3) * 4;     // 0,4,8,12
    int lkB   = tid >> 4;          // 0..15
    int ln4B  = (tid & 15) * 4;    // 0..60

    const float* Aptr = A + (size_t)(bm + lrowA) * K + lk4A;
    const float* Bptr = Bw + (size_t)lkB * N + bn + ln4B;

    float acc[4][4] = {};
    for (int kt = 0; kt < K; kt += 16) {
        float4 av = *(const float4*)(Aptr + kt);
        float4 bv = *(const float4*)(Bptr + (size_t)kt * N);
        As[lk4A + 0][lrowA] = av.x;
        As[lk4A + 1][lrowA] = av.y;
        As[lk4A + 2][lrowA] = av.z;
        As[lk4A + 3][lrowA] = av.w;
        *(float4*)&Bs[lkB][ln4B] = bv;
        __syncthreads();
#pragma unroll
        for (int k = 0; k < 16; ++k) {
            float4 a4 = *(const float4*)&As[k][ty * 4];
            float4 b4 = *(const float4*)&Bs[k][tx * 4];
            float ar[4] = {a4.x, a4.y, a4.z, a4.w};
            float br[4] = {b4.x, b4.y, b4.z, b4.w};
#pragma unroll
            for (int i = 0; i < 4; ++i)
#pragma unroll
                for (int j = 0; j < 4; ++j)
                    acc[i][j] = fmaf(ar[i], br[j], acc[i][j]);
        }
        __syncthreads();
    }
#pragma unroll
    for (int i = 0; i < 4; ++i) {
        int row = bm + ty * 4 + i;
#pragma unroll
        for (int j = 0; j < 4; ++j) {
            int col = bn + tx * 4 + j;
            float v = acc[i][j] + bias[col];
            if (act == 1)
                v = 0.5f * v * (1.0f + erff(v * 0.7071067811865476f));
            C[(size_t)row * N + col] = v;
        }
    }
}

// ---------------- banded flash attention ----------------
// grid (S/64, H, B), 256 threads. 64-query tile, 5 key tiles of 64.
#define APITCH 68
__global__ __launch_bounds__(256) void attn_kernel(
    const float* __restrict__ Q, const float* __restrict__ K,
    const float* __restrict__ V, const int* __restrict__ am,
    float* __restrict__ Aout)
{
    extern __shared__ float sm[];
    float* Qts = sm;                       // [64 d][68] transposed, scaled
    float* Kts = sm + 64 * APITCH;         // [64 d][68] transposed; reused as Pts [64 key][68]
    float* Vs  = sm + 2 * 64 * APITCH;     // [64 key][68] natural
    int*   kval = (int*)(sm + 3 * 64 * APITCH);

    int tid = threadIdx.x;
    int tx = tid & 15, ty = tid >> 4;
    int qt = blockIdx.x, h = blockIdx.y, b = blockIdx.z;
    int q0 = qt * 64;
    const size_t base = ((size_t)b * SS) * HID + (size_t)h * HD;

    for (int idx = tid; idx < 64 * 64; idx += 256) {
        int r = idx >> 6, d = idx & 63;
        Qts[d * APITCH + r] = Q[base + (size_t)(q0 + r) * HID + d] * 0.125f;
    }

    float mrow[4], lrow[4], O[4][4];
#pragma unroll
    for (int i = 0; i < 4; ++i) {
        mrow[i] = -INFINITY; lrow[i] = 0.f;
#pragma unroll
        for (int j = 0; j < 4; ++j) O[i][j] = 0.f;
    }

    for (int kt = 0; kt < 5; ++kt) {
        int ks = q0 - 128 + kt * 64;
        __syncthreads();   // Qts ready (iter 0); prev-iter Pts/Vs reads done
        for (int idx = tid; idx < 64 * 64; idx += 256) {
            int r = idx >> 6, d = idx & 63;
            int kj = ks + r;
            float kv = 0.f, vv = 0.f;
            if ((unsigned)kj < (unsigned)SS) {
                kv = K[base + (size_t)kj * HID + d];
                vv = V[base + (size_t)kj * HID + d];
            }
            Kts[d * APITCH + r] = kv;
            Vs[r * APITCH + d]  = vv;
        }
        if (tid < 64) {
            int kj = ks + tid;
            kval[tid] = ((unsigned)kj < (unsigned)SS) && (am[(size_t)b * SS + kj] != 0);
        }
        __syncthreads();

        float acc[4][4] = {};
#pragma unroll 8
        for (int d = 0; d < 64; ++d) {
            float4 a4 = *(const float4*)&Qts[d * APITCH + 4 * ty];
            float4 b4 = *(const float4*)&Kts[d * APITCH + 4 * tx];
            float ar[4] = {a4.x, a4.y, a4.z, a4.w};
            float br[4] = {b4.x, b4.y, b4.z, b4.w};
#pragma unroll
            for (int i = 0; i < 4; ++i)
#pragma unroll
                for (int j = 0; j < 4; ++j)
                    acc[i][j] = fmaf(ar[i], br[j], acc[i][j]);
        }
        __syncthreads();   // Kts reads done; safe to overwrite with P

        float p[4][4];
#pragma unroll
        for (int i = 0; i < 4; ++i) {
            int qi = q0 + ty * 4 + i;
            float rmax = -INFINITY;
#pragma unroll
            for (int j = 0; j < 4; ++j) {
                int kc = tx * 4 + j;
                int kj = ks + kc;
                bool valid = kval[kc] && (kj >= qi - WIN) && (kj <= qi + WIN);
                float sc = valid ? acc[i][j] : -1e9f;
                acc[i][j] = sc;
                rmax = fmaxf(rmax, sc);
            }
#pragma unroll
            for (int o = 8; o; o >>= 1)
                rmax = fmaxf(rmax, __shfl_xor_sync(0xffffffffu, rmax, o, 16));
            float mnew = fmaxf(mrow[i], rmax);
            float scal = __expf(mrow[i] - mnew);
            mrow[i] = mnew;
            float ls = 0.f;
#pragma unroll
            for (int j = 0; j < 4; ++j) {
                float pv = __expf(acc[i][j] - mnew);
                p[i][j] = pv;
                ls += pv;
            }
#pragma unroll
            for (int o = 8; o; o >>= 1)
                ls += __shfl_xor_sync(0xffffffffu, ls, o, 16);
            lrow[i] = lrow[i] * scal + ls;
#pragma unroll
            for (int j = 0; j < 4; ++j) {
                O[i][j] *= scal;
                // Pts transposed: [key][query]
                Kts[(tx * 4 + j) * APITCH + ty * 4 + i] = p[i][j];
            }
        }
        __syncthreads();   // Pts written

#pragma unroll 8
        for (int k = 0; k < 64; ++k) {
            float4 p4 = *(const float4*)&Kts[k * APITCH + 4 * ty];
            float4 v4 = *(const float4*)&Vs[k * APITCH + 4 * tx];
            float pr[4] = {p4.x, p4.y, p4.z, p4.w};
            float vr[4] = {v4.x, v4.y, v4.z, v4.w};
#pragma unroll
            for (int i = 0; i < 4; ++i)
#pragma unroll
                for (int j = 0; j < 4; ++j)
                    O[i][j] = fmaf(pr[i], vr[j], O[i][j]);
        }
    }

#pragma unroll
    for (int i = 0; i < 4; ++i) {
        float rl = (lrow[i] > 0.f) ? (1.f / lrow[i]) : 0.f;
#pragma unroll
        for (int j = 0; j < 4; ++j)
            Aout[base + (size_t)(q0 + ty * 4 + i) * HID + tx * 4 + j] = O[i][j] * rl;
    }
}

// ---------------- final projection + sigmoid ----------------
__global__ __launch_bounds__(256) void final_kernel(
    const float* __restrict__ h, const float* __restrict__ Wp,
    const float* __restrict__ bp, float* __restrict__ out)
{
    int gtid = blockIdx.x * 256 + threadIdx.x;
    int row = gtid >> 5;
    int lane = gtid & 31;
    if (row >= MROWS) return;
    float s = 0.f;
    for (int k = lane; k < HID; k += 32)
        s = fmaf(h[(size_t)row * HID + k], Wp[k], s);
#pragma unroll
    for (int o = 16; o; o >>= 1) s += __shfl_xor_sync(0xffffffffu, s, o);
    if (lane == 0)
        out[row] = 1.f / (1.f + expf(-(s + bp[0])));
}

// ---------------- host orchestration ----------------
extern "C" void kernel_launch(void* const* d_in, const int* in_sizes, int n_in,
                              void* d_out, int out_size)
{
    const float* emb     = (const float*)d_in[0];
    const int*   amask   = (const int*)  d_in[1];
    const float* pos     = (const float*)d_in[2];
    const float* tok     = (const float*)d_in[3];
    const float* eln_g   = (const float*)d_in[4];
    const float* eln_b   = (const float*)d_in[5];
    const float* Wq      = (const float*)d_in[6];
    const float* bq      = (const float*)d_in[7];
    const float* Wk      = (const float*)d_in[8];
    const float* bk      = (const float*)d_in[9];
    const float* Wv      = (const float*)d_in[10];
    const float* bv      = (const float*)d_in[11];
    const float* Wo      = (const float*)d_in[12];
    const float* bo      = (const float*)d_in[13];
    const float* ln1_g   = (const float*)d_in[14];
    const float* ln1_b   = (const float*)d_in[15];
    const float* Wi      = (const float*)d_in[16];
    const float* bi      = (const float*)d_in[17];
    const float* Wf      = (const float*)d_in[18];
    const float* bf      = (const float*)d_in[19];
    const float* ln2_g   = (const float*)d_in[20];
    const float* ln2_b   = (const float*)d_in[21];
    const float* Wp      = (const float*)d_in[22];
    const float* bp      = (const float*)d_in[23];

    float *h_, *q_, *k_, *v_, *a_, *t_, *f_;
    cudaGetSymbolAddress((void**)&h_, g_h);
    cudaGetSymbolAddress((void**)&q_, g_q);
    cudaGetSymbolAddress((void**)&k_, g_k);
    cudaGetSymbolAddress((void**)&v_, g_v);
    cudaGetSymbolAddress((void**)&a_, g_a);
    cudaGetSymbolAddress((void**)&t_, g_t);
    cudaGetSymbolAddress((void**)&f_, g_f);

    const int attn_smem = (3 * 64 * APITCH) * 4 + 64 * 4;  // 52480 B
    cudaFuncSetAttribute(attn_kernel,
                         cudaFuncAttributeMaxDynamicSharedMemorySize, attn_smem);

    embed_ln_kernel<<<MROWS, 256>>>(emb, pos, tok, eln_g, eln_b, h_);

    const size_t WSQ = (size_t)HID * HID;       // 768*768
    const size_t WSI = (size_t)HID * 4 * HID;   // 768*3072

    for (int l = 0; l < LAYERS; ++l) {
        dim3 g1(HID / 64, MROWS / 64);
        sgemm_kernel<<<g1, 256>>>(h_, Wq + l * WSQ, bq + l * HID, q_, MROWS, HID, HID, 0);
        sgemm_kernel<<<g1, 256>>>(h_, Wk + l * WSQ, bk + l * HID, k_, MROWS, HID, HID, 0);
        sgemm_kernel<<<g1, 256>>>(h_, Wv + l * WSQ, bv + l * HID, v_, MROWS, HID, HID, 0);

        dim3 ga(SS / 64, HEADS, BB);
        attn_kernel<<<ga, 256, attn_smem>>>(q_, k_, v_, amask, a_);

        sgemm_kernel<<<g1, 256>>>(a_, Wo + l * WSQ, bo + l * HID, t_, MROWS, HID, HID, 0);
        add_ln_kernel<<<MROWS, 256>>>(h_, t_, ln1_g + l * HID, ln1_b + l * HID, h_);

        dim3 g2(4 * HID / 64, MROWS / 64);
        sgemm_kernel<<<g2, 256>>>(h_, Wi + l * WSI, bi + (size_t)l * 4 * HID, f_,
                                  MROWS, 4 * HID, HID, 1);
        sgemm_kernel<<<g1, 256>>>(f_, Wf + l * WSI, bf + l * HID, t_,
                                  MROWS, HID, 4 * HID, 0);
        add_ln_kernel<<<MROWS, 256>>>(h_, t_, ln2_g + l * HID, ln2_b + l * HID, h_);
    }

    final_kernel<<<(MROWS * 32 + 255) / 256, 256>>>(h_, Wp, bp, (float*)d_out);
}

// round 3
// speedup vs baseline: 2.0622x; 2.0622x over previous
#include <cuda_runtime.h>
#include <math.h>
#include <stdint.h>

// ---------------- problem constants ----------------
#define BB      2
#define SS      4096
#define HID     768
#define LAYERS  4
#define HEADS   12
#define HD      64
#define WIN     128          // one-sided window
#define MROWS   (BB*SS)      // 8192 token rows

// ---------------- scratch (device globals; no allocation) ----------------
__device__ float g_h[MROWS * HID];
__device__ float g_q[MROWS * HID];
__device__ float g_k[MROWS * HID];
__device__ float g_v[MROWS * HID];
__device__ float g_a[MROWS * HID];
__device__ float g_t[MROWS * HID];
__device__ float g_f[MROWS * 4 * HID];

// =======================================================================
// helpers
// =======================================================================
__device__ __forceinline__ uint32_t f2tf32(float x) {
    uint32_t u;
    asm("cvt.rna.tf32.f32 %0, %1;" : "=r"(u) : "f"(x));
    return u;
}
__device__ __forceinline__ void mma_tf32(
    float& d0, float& d1, float& d2, float& d3,
    uint32_t a0, uint32_t a1, uint32_t a2, uint32_t a3,
    uint32_t b0, uint32_t b1)
{
    asm volatile(
        "mma.sync.aligned.m16n8k8.row.col.f32.tf32.tf32.f32 "
        "{%0,%1,%2,%3}, {%4,%5,%6,%7}, {%8,%9}, {%0,%1,%2,%3};"
        : "+f"(d0), "+f"(d1), "+f"(d2), "+f"(d3)
        : "r"(a0), "r"(a1), "r"(a2), "r"(a3), "r"(b0), "r"(b1));
}

// =======================================================================
// tf32 mma.sync GEMM: C[M,N] = A[M,K] * W[K,N] + bias, optional GELU
// block tile 128x128, BK=32, 256 threads (8 warps), warp tile 32x64.
// smem: A [128m][32k] XOR-swizzled (4096 u32/buf);
//       B [32k][128n] pitch 136 (4352 u32/buf); double buffered.
// =======================================================================
#define BPITCH 136
#define GEMM_SMEM_BYTES ((2*4096 + 2*32*BPITCH) * 4)   // 67584

__global__ __launch_bounds__(256) void gemm_tc_kernel(
    const float* __restrict__ A, const float* __restrict__ Bw,
    const float* __restrict__ bias, float* __restrict__ C,
    int M, int N, int K, int act)
{
    extern __shared__ uint32_t smu[];
    uint32_t* As[2] = { smu,            smu + 4096 };
    uint32_t* Bs[2] = { smu + 2*4096,   smu + 2*4096 + 32*BPITCH };

    const int tid  = threadIdx.x;
    const int lane = tid & 31;
    const int wid  = tid >> 5;
    const int lm   = lane >> 2;        // 0..7
    const int lk   = lane & 3;         // 0..3
    const int warp_m = (wid >> 1) * 32;
    const int warp_n = (wid & 1) * 64;
    const int bm = blockIdx.y * 128;
    const int bn = blockIdx.x * 128;

    // global A load: row ar+32*i, cols ac4..ac4+3 of the current chunk
    const int ar  = tid >> 3;          // 0..31
    const int ac4 = (tid & 7) * 4;     // 0..28
    const float* Ag = A + (size_t)(bm + ar) * K + ac4;
    // global B load: chunk-row bkk+8*i, cols bn4..bn4+3
    const int bkk = tid >> 5;          // 0..7
    const int bn4 = (tid & 31) * 4;    // 0..124
    const float* Bg = Bw + (size_t)bkk * N + bn + bn4;

    float acc[2][8][4];
#pragma unroll
    for (int mt = 0; mt < 2; ++mt)
#pragma unroll
        for (int nt = 0; nt < 8; ++nt)
#pragma unroll
            for (int c = 0; c < 4; ++c) acc[mt][nt][c] = 0.f;

    const int NC = K >> 5;
    float4 pa[4], pb[4];

    // ---- prologue: load chunk 0 ----
#pragma unroll
    for (int i = 0; i < 4; ++i)
        pa[i] = *(const float4*)(Ag + (size_t)(32 * i) * K);
#pragma unroll
    for (int i = 0; i < 4; ++i)
        pb[i] = *(const float4*)(Bg + (size_t)(8 * i) * N);
    {
#pragma unroll
        for (int i = 0; i < 4; ++i) {
            int r = ar + 32 * i;
            uint32_t off = r * 32 + (((ac4 >> 2) ^ (r & 7)) << 2);
            uint4 t;
            t.x = f2tf32(pa[i].x); t.y = f2tf32(pa[i].y);
            t.z = f2tf32(pa[i].z); t.w = f2tf32(pa[i].w);
            *(uint4*)(As[0] + off) = t;
        }
#pragma unroll
        for (int i = 0; i < 4; ++i) {
            uint32_t off = (bkk + 8 * i) * BPITCH + bn4;
            uint4 t;
            t.x = f2tf32(pb[i].x); t.y = f2tf32(pb[i].y);
            t.z = f2tf32(pb[i].z); t.w = f2tf32(pb[i].w);
            *(uint4*)(Bs[0] + off) = t;
        }
    }
    __syncthreads();

    for (int c = 0; c < NC; ++c) {
        const int buf = c & 1;
        const bool more = (c + 1 < NC);
        if (more) {
            const int k0 = (c + 1) * 32;
#pragma unroll
            for (int i = 0; i < 4; ++i)
                pa[i] = *(const float4*)(Ag + (size_t)(32 * i) * K + k0);
#pragma unroll
            for (int i = 0; i < 4; ++i)
                pb[i] = *(const float4*)(Bg + (size_t)(k0 + 8 * i) * N);
        }

        const uint32_t* sA = As[buf];
        const uint32_t* sB = Bs[buf];
#pragma unroll
        for (int k8 = 0; k8 < 32; k8 += 8) {
            const int g0 = (k8 >> 2) ^ lm;       // swizzle group for k8..k8+3
            const int g1 = ((k8 >> 2) + 1) ^ lm; // for k8+4..k8+7
            uint32_t a[2][4];
#pragma unroll
            for (int mt = 0; mt < 2; ++mt) {
                int m0 = warp_m + mt * 16 + lm;
                a[mt][0] = sA[m0 * 32 + (g0 << 2) + lk];
                a[mt][1] = sA[(m0 + 8) * 32 + (g0 << 2) + lk];
                a[mt][2] = sA[m0 * 32 + (g1 << 2) + lk];
                a[mt][3] = sA[(m0 + 8) * 32 + (g1 << 2) + lk];
            }
            uint32_t b[8][2];
#pragma unroll
            for (int nt = 0; nt < 8; ++nt) {
                int n0 = warp_n + nt * 8 + lm;
                b[nt][0] = sB[(k8 + lk) * BPITCH + n0];
                b[nt][1] = sB[(k8 + 4 + lk) * BPITCH + n0];
            }
#pragma unroll
            for (int mt = 0; mt < 2; ++mt)
#pragma unroll
                for (int nt = 0; nt < 8; ++nt)
                    mma_tf32(acc[mt][nt][0], acc[mt][nt][1],
                             acc[mt][nt][2], acc[mt][nt][3],
                             a[mt][0], a[mt][1], a[mt][2], a[mt][3],
                             b[nt][0], b[nt][1]);
        }

        if (more) {
            uint32_t* dA = As[buf ^ 1];
            uint32_t* dB = Bs[buf ^ 1];
#pragma unroll
            for (int i = 0; i < 4; ++i) {
                int r = ar + 32 * i;
                uint32_t off = r * 32 + (((ac4 >> 2) ^ (r & 7)) << 2);
                uint4 t;
                t.x = f2tf32(pa[i].x); t.y = f2tf32(pa[i].y);
                t.z = f2tf32(pa[i].z); t.w = f2tf32(pa[i].w);
                *(uint4*)(dA + off) = t;
            }
#pragma unroll
            for (int i = 0; i < 4; ++i) {
                uint32_t off = (bkk + 8 * i) * BPITCH + bn4;
                uint4 t;
                t.x = f2tf32(pb[i].x); t.y = f2tf32(pb[i].y);
                t.z = f2tf32(pb[i].z); t.w = f2tf32(pb[i].w);
                *(uint4*)(dB + off) = t;
            }
        }
        __syncthreads();
    }

    // ---- epilogue ----
#pragma unroll
    for (int mt = 0; mt < 2; ++mt) {
        int row0 = bm + warp_m + mt * 16 + lm;
#pragma unroll
        for (int nt = 0; nt < 8; ++nt) {
            int col = bn + warp_n + nt * 8 + 2 * lk;
            float b0 = bias[col], b1 = bias[col + 1];
            float v0 = acc[mt][nt][0] + b0;
            float v1 = acc[mt][nt][1] + b1;
            float v2 = acc[mt][nt][2] + b0;
            float v3 = acc[mt][nt][3] + b1;
            if (act == 1) {
                v0 = 0.5f * v0 * (1.0f + erff(v0 * 0.7071067811865476f));
                v1 = 0.5f * v1 * (1.0f + erff(v1 * 0.7071067811865476f));
                v2 = 0.5f * v2 * (1.0f + erff(v2 * 0.7071067811865476f));
                v3 = 0.5f * v3 * (1.0f + erff(v3 * 0.7071067811865476f));
            }
            *(float2*)(C + (size_t)row0 * N + col) = make_float2(v0, v1);
            *(float2*)(C + (size_t)(row0 + 8) * N + col) = make_float2(v2, v3);
        }
    }
}

// =======================================================================
// block reduction helper (768-wide rows, 256 threads)
// =======================================================================
__device__ __forceinline__ float block_sum(float v, float* sh) {
    __syncthreads();
    int lane = threadIdx.x & 31, w = threadIdx.x >> 5;
#pragma unroll
    for (int o = 16; o; o >>= 1) v += __shfl_xor_sync(0xffffffffu, v, o);
    if (lane == 0) sh[w] = v;
    __syncthreads();
    if (w == 0) {
        float t = (lane < 8) ? sh[lane] : 0.f;
#pragma unroll
        for (int o = 4; o; o >>= 1) t += __shfl_xor_sync(0xffffffffu, t, o);
        if (lane == 0) sh[0] = t;
    }
    __syncthreads();
    return sh[0];
}

// ---------------- embeddings + LN ----------------
__global__ __launch_bounds__(256) void embed_ln_kernel(
    const float* __restrict__ emb, const float* __restrict__ pos,
    const float* __restrict__ tok, const float* __restrict__ g,
    const float* __restrict__ b, float* __restrict__ out)
{
    __shared__ float sh[8];
    int row = blockIdx.x;
    int s = row & (SS - 1);
    int tid = threadIdx.x;
    float x[3];
#pragma unroll
    for (int i = 0; i < 3; ++i) {
        int j = tid + i * 256;
        x[i] = emb[(size_t)row * HID + j] + pos[(size_t)(s + 1) * HID + j] + tok[j];
    }
    float mean = block_sum(x[0] + x[1] + x[2], sh) * (1.f / HID);
    float d2 = 0.f;
#pragma unroll
    for (int i = 0; i < 3; ++i) { float d = x[i] - mean; d2 += d * d; }
    float var = block_sum(d2, sh) * (1.f / HID);
    float rs = rsqrtf(var + 1e-12f);
#pragma unroll
    for (int i = 0; i < 3; ++i) {
        int j = tid + i * 256;
        out[(size_t)row * HID + j] = (x[i] - mean) * rs * g[j] + b[j];
    }
}

// ---------------- residual add + LN ----------------
__global__ __launch_bounds__(256) void add_ln_kernel(
    const float* __restrict__ hin, const float* __restrict__ xin,
    const float* __restrict__ g, const float* __restrict__ b,
    float* __restrict__ out)
{
    __shared__ float sh[8];
    int row = blockIdx.x;
    int tid = threadIdx.x;
    float x[3];
#pragma unroll
    for (int i = 0; i < 3; ++i) {
        int j = tid + i * 256;
        x[i] = hin[(size_t)row * HID + j] + xin[(size_t)row * HID + j];
    }
    float mean = block_sum(x[0] + x[1] + x[2], sh) * (1.f / HID);
    float d2 = 0.f;
#pragma unroll
    for (int i = 0; i < 3; ++i) { float d = x[i] - mean; d2 += d * d; }
    float var = block_sum(d2, sh) * (1.f / HID);
    float rs = rsqrtf(var + 1e-12f);
#pragma unroll
    for (int i = 0; i < 3; ++i) {
        int j = tid + i * 256;
        out[(size_t)row * HID + j] = (x[i] - mean) * rs * g[j] + b[j];
    }
}

// ---------------- banded flash attention ----------------
#define APITCH 68
__global__ __launch_bounds__(256) void attn_kernel(
    const float* __restrict__ Q, const float* __restrict__ K,
    const float* __restrict__ V, const int* __restrict__ am,
    float* __restrict__ Aout)
{
    extern __shared__ float sm[];
    float* Qts = sm;
    float* Kts = sm + 64 * APITCH;
    float* Vs  = sm + 2 * 64 * APITCH;
    int*   kval = (int*)(sm + 3 * 64 * APITCH);

    int tid = threadIdx.x;
    int tx = tid & 15, ty = tid >> 4;
    int qt = blockIdx.x, h = blockIdx.y, b = blockIdx.z;
    int q0 = qt * 64;
    const size_t base = ((size_t)b * SS) * HID + (size_t)h * HD;

    for (int idx = tid; idx < 64 * 64; idx += 256) {
        int r = idx >> 6, d = idx & 63;
        Qts[d * APITCH + r] = Q[base + (size_t)(q0 + r) * HID + d] * 0.125f;
    }

    float mrow[4], lrow[4], O[4][4];
#pragma unroll
    for (int i = 0; i < 4; ++i) {
        mrow[i] = -INFINITY; lrow[i] = 0.f;
#pragma unroll
        for (int j = 0; j < 4; ++j) O[i][j] = 0.f;
    }

    for (int kt = 0; kt < 5; ++kt) {
        int ks = q0 - 128 + kt * 64;
        __syncthreads();
        for (int idx = tid; idx < 64 * 64; idx += 256) {
            int r = idx >> 6, d = idx & 63;
            int kj = ks + r;
            float kv = 0.f, vv = 0.f;
            if ((unsigned)kj < (unsigned)SS) {
                kv = K[base + (size_t)kj * HID + d];
                vv = V[base + (size_t)kj * HID + d];
            }
            Kts[d * APITCH + r] = kv;
            Vs[r * APITCH + d]  = vv;
        }
        if (tid < 64) {
            int kj = ks + tid;
            kval[tid] = ((unsigned)kj < (unsigned)SS) && (am[(size_t)b * SS + kj] != 0);
        }
        __syncthreads();

        float acc[4][4] = {};
#pragma unroll 8
        for (int d = 0; d < 64; ++d) {
            float4 a4 = *(const float4*)&Qts[d * APITCH + 4 * ty];
            float4 b4 = *(const float4*)&Kts[d * APITCH + 4 * tx];
            float ar[4] = {a4.x, a4.y, a4.z, a4.w};
            float br[4] = {b4.x, b4.y, b4.z, b4.w};
#pragma unroll
            for (int i = 0; i < 4; ++i)
#pragma unroll
                for (int j = 0; j < 4; ++j)
                    acc[i][j] = fmaf(ar[i], br[j], acc[i][j]);
        }
        __syncthreads();

        float p[4][4];
#pragma unroll
        for (int i = 0; i < 4; ++i) {
            int qi = q0 + ty * 4 + i;
            float rmax = -INFINITY;
#pragma unroll
            for (int j = 0; j < 4; ++j) {
                int kc = tx * 4 + j;
                int kj = ks + kc;
                bool valid = kval[kc] && (kj >= qi - WIN) && (kj <= qi + WIN);
                float sc = valid ? acc[i][j] : -1e9f;
                acc[i][j] = sc;
                rmax = fmaxf(rmax, sc);
            }
#pragma unroll
            for (int o = 8; o; o >>= 1)
                rmax = fmaxf(rmax, __shfl_xor_sync(0xffffffffu, rmax, o, 16));
            float mnew = fmaxf(mrow[i], rmax);
            float scal = __expf(mrow[i] - mnew);
            mrow[i] = mnew;
            float ls = 0.f;
#pragma unroll
            for (int j = 0; j < 4; ++j) {
                float pv = __expf(acc[i][j] - mnew);
                p[i][j] = pv;
                ls += pv;
            }
#pragma unroll
            for (int o = 8; o; o >>= 1)
                ls += __shfl_xor_sync(0xffffffffu, ls, o, 16);
            lrow[i] = lrow[i] * scal + ls;
#pragma unroll
            for (int j = 0; j < 4; ++j) {
                O[i][j] *= scal;
                Kts[(tx * 4 + j) * APITCH + ty * 4 + i] = p[i][j];
            }
        }
        __syncthreads();

#pragma unroll 8
        for (int k = 0; k < 64; ++k) {
            float4 p4 = *(const float4*)&Kts[k * APITCH + 4 * ty];
            float4 v4 = *(const float4*)&Vs[k * APITCH + 4 * tx];
            float pr[4] = {p4.x, p4.y, p4.z, p4.w};
            float vr[4] = {v4.x, v4.y, v4.z, v4.w};
#pragma unroll
            for (int i = 0; i < 4; ++i)
#pragma unroll
                for (int j = 0; j < 4; ++j)
                    O[i][j] = fmaf(pr[i], vr[j], O[i][j]);
        }
    }

#pragma unroll
    for (int i = 0; i < 4; ++i) {
        float rl = (lrow[i] > 0.f) ? (1.f / lrow[i]) : 0.f;
#pragma unroll
        for (int j = 0; j < 4; ++j)
            Aout[base + (size_t)(q0 + ty * 4 + i) * HID + tx * 4 + j] = O[i][j] * rl;
    }
}

// ---------------- final projection + sigmoid ----------------
__global__ __launch_bounds__(256) void final_kernel(
    const float* __restrict__ h, const float* __restrict__ Wp,
    const float* __restrict__ bp, float* __restrict__ out)
{
    int gtid = blockIdx.x * 256 + threadIdx.x;
    int row = gtid >> 5;
    int lane = gtid & 31;
    if (row >= MROWS) return;
    float s = 0.f;
    for (int k = lane; k < HID; k += 32)
        s = fmaf(h[(size_t)row * HID + k], Wp[k], s);
#pragma unroll
    for (int o = 16; o; o >>= 1) s += __shfl_xor_sync(0xffffffffu, s, o);
    if (lane == 0)
        out[row] = 1.f / (1.f + expf(-(s + bp[0])));
}

// ---------------- host orchestration ----------------
extern "C" void kernel_launch(void* const* d_in, const int* in_sizes, int n_in,
                              void* d_out, int out_size)
{
    const float* emb     = (const float*)d_in[0];
    const int*   amask   = (const int*)  d_in[1];
    const float* pos     = (const float*)d_in[2];
    const float* tok     = (const float*)d_in[3];
    const float* eln_g   = (const float*)d_in[4];
    const float* eln_b   = (const float*)d_in[5];
    const float* Wq      = (const float*)d_in[6];
    const float* bq      = (const float*)d_in[7];
    const float* Wk      = (const float*)d_in[8];
    const float* bk      = (const float*)d_in[9];
    const float* Wv      = (const float*)d_in[10];
    const float* bv      = (const float*)d_in[11];
    const float* Wo      = (const float*)d_in[12];
    const float* bo      = (const float*)d_in[13];
    const float* ln1_g   = (const float*)d_in[14];
    const float* ln1_b   = (const float*)d_in[15];
    const float* Wi      = (const float*)d_in[16];
    const float* bi      = (const float*)d_in[17];
    const float* Wf      = (const float*)d_in[18];
    const float* bf      = (const float*)d_in[19];
    const float* ln2_g   = (const float*)d_in[20];
    const float* ln2_b   = (const float*)d_in[21];
    const float* Wp      = (const float*)d_in[22];
    const float* bp      = (const float*)d_in[23];

    float *h_, *q_, *k_, *v_, *a_, *t_, *f_;
    cudaGetSymbolAddress((void**)&h_, g_h);
    cudaGetSymbolAddress((void**)&q_, g_q);
    cudaGetSymbolAddress((void**)&k_, g_k);
    cudaGetSymbolAddress((void**)&v_, g_v);
    cudaGetSymbolAddress((void**)&a_, g_a);
    cudaGetSymbolAddress((void**)&t_, g_t);
    cudaGetSymbolAddress((void**)&f_, g_f);

    const int attn_smem = (3 * 64 * APITCH) * 4 + 64 * 4;  // 52480 B
    cudaFuncSetAttribute(attn_kernel,
                         cudaFuncAttributeMaxDynamicSharedMemorySize, attn_smem);
    cudaFuncSetAttribute(gemm_tc_kernel,
                         cudaFuncAttributeMaxDynamicSharedMemorySize, GEMM_SMEM_BYTES);

    embed_ln_kernel<<<MROWS, 256>>>(emb, pos, tok, eln_g, eln_b, h_);

    const size_t WSQ = (size_t)HID * HID;
    const size_t WSI = (size_t)HID * 4 * HID;

    for (int l = 0; l < LAYERS; ++l) {
        dim3 g1(HID / 128, MROWS / 128);          // (6, 64)
        gemm_tc_kernel<<<g1, 256, GEMM_SMEM_BYTES>>>(h_, Wq + l * WSQ, bq + l * HID, q_, MROWS, HID, HID, 0);
        gemm_tc_kernel<<<g1, 256, GEMM_SMEM_BYTES>>>(h_, Wk + l * WSQ, bk + l * HID, k_, MROWS, HID, HID, 0);
        gemm_tc_kernel<<<g1, 256, GEMM_SMEM_BYTES>>>(h_, Wv + l * WSQ, bv + l * HID, v_, MROWS, HID, HID, 0);

        dim3 ga(SS / 64, HEADS, BB);
        attn_kernel<<<ga, 256, attn_smem>>>(q_, k_, v_, amask, a_);

        gemm_tc_kernel<<<g1, 256, GEMM_SMEM_BYTES>>>(a_, Wo + l * WSQ, bo + l * HID, t_, MROWS, HID, HID, 0);
        add_ln_kernel<<<MROWS, 256>>>(h_, t_, ln1_g + l * HID, ln1_b + l * HID, h_);

        dim3 g2(4 * HID / 128, MROWS / 128);      // (24, 64)
        gemm_tc_kernel<<<g2, 256, GEMM_SMEM_BYTES>>>(h_, Wi + l * WSI, bi + (size_t)l * 4 * HID, f_,
                                                     MROWS, 4 * HID, HID, 1);
        gemm_tc_kernel<<<g1, 256, GEMM_SMEM_BYTES>>>(f_, Wf + l * WSI, bf + l * HID, t_,
                                                     MROWS, HID, 4 * HID, 0);
        add_ln_kernel<<<MROWS, 256>>>(h_, t_, ln2_g + l * HID, ln2_b + l * HID, h_);
    }

    final_kernel<<<(MROWS * 32 + 255) / 256, 256>>>(h_, Wp, bp, (float*)d_out);
}

// round 5
// speedup vs baseline: 3.5653x; 1.7289x over previous
#include <cuda_runtime.h>
#include <math.h>
#include <stdint.h>

// ---------------- problem constants ----------------
#define BB      2
#define SS      4096
#define HID     768
#define LAYERS  4
#define HEADS   12
#define HD      64
#define WIN     128          // one-sided window
#define MROWS   (BB*SS)      // 8192 token rows
#define QS      2304         // fused QKV row stride

// ---------------- scratch (device globals; no allocation) ----------------
__device__ __align__(256) float g_h [MROWS * HID];
__device__ __align__(256) float g_hr[MROWS * HID];     // tf32-rounded copy of h
__device__ __align__(256) float g_qkv[MROWS * QS];
__device__ __align__(256) float g_a [MROWS * HID];
__device__ __align__(256) float g_t [MROWS * HID];
__device__ __align__(256) float g_f [MROWS * 4 * HID];
// rounded weights
__device__ __align__(256) float g_wqkv[LAYERS * HID * QS];
__device__ __align__(256) float g_bqkv[LAYERS * QS];
__device__ __align__(256) float g_wo [LAYERS * HID * HID];
__device__ __align__(256) float g_wi [LAYERS * HID * 4 * HID];
__device__ __align__(256) float g_wf [LAYERS * 4 * HID * HID];

// =======================================================================
// helpers
// =======================================================================
__device__ __forceinline__ float rtf(float x) {
    uint32_t u;
    asm("cvt.rna.tf32.f32 %0, %1;" : "=r"(u) : "f"(x));
    return __uint_as_float(u);
}
__device__ __forceinline__ void mma_tf32(
    float& d0, float& d1, float& d2, float& d3,
    uint32_t a0, uint32_t a1, uint32_t a2, uint32_t a3,
    uint32_t b0, uint32_t b1)
{
    asm volatile(
        "mma.sync.aligned.m16n8k8.row.col.f32.tf32.tf32.f32 "
        "{%0,%1,%2,%3}, {%4,%5,%6,%7}, {%8,%9}, {%0,%1,%2,%3};"
        : "+f"(d0), "+f"(d1), "+f"(d2), "+f"(d3)
        : "r"(a0), "r"(a1), "r"(a2), "r"(a3), "r"(b0), "r"(b1));
}
__device__ __forceinline__ void cp16(uint32_t dst, const void* src) {
    asm volatile("cp.async.cg.shared.global [%0], [%1], 16;"
                 :: "r"(dst), "l"(src));
}

// =======================================================================
// tf32 mma.sync GEMM, cp.async 3-stage pipeline.
// C[M,N] = A[M,K]*W[K,N] + bias, act=1 -> GELU + tf32-round output.
// block 128x128, BK=32, 256 threads (8 warps), warp tile 32x64.
// A smem [128m][32k] XOR-swizzled; B smem [32k][128n] pitch 136.
// Inputs A and W must already be tf32-rounded values (fp32 container).
// =======================================================================
#define BPITCH 136
#define A_WORDS (128*32)
#define B_WORDS (32*BPITCH)
#define STG_WORDS (A_WORDS + B_WORDS)
#define GEMM_SMEM_BYTES (3 * STG_WORDS * 4)   // 101376

__global__ __launch_bounds__(256, 2) void gemm_tc_kernel(
    const float* __restrict__ A, const float* __restrict__ Bw,
    const float* __restrict__ bias, float* __restrict__ C,
    int M, int N, int K, int act)
{
    extern __shared__ uint32_t smu[];
    uint32_t smem_base = (uint32_t)__cvta_generic_to_shared(smu);

    const int tid  = threadIdx.x;
    const int lane = tid & 31;
    const int wid  = tid >> 5;
    const int lm   = lane >> 2;        // 0..7
    const int lk   = lane & 3;         // 0..3
    const int warp_m = (wid >> 1) * 32;
    const int warp_n = (wid & 1) * 64;
    const int bm = blockIdx.y * 128;
    const int bn = blockIdx.x * 128;

    // cp.async thread mapping
    const int ar = tid >> 3;                 // 0..31 (A row group)
    const int ac = tid & 7;                  // A k-quad
    const uint32_t a_sw = (uint32_t)((ac ^ (ar & 7)) << 2);
    const float* Ag = A + (size_t)(bm + ar) * K + ac * 4;
    const int bkk = tid >> 5;                // 0..7
    const int bn4 = (tid & 31) * 4;
    const float* Bg = Bw + (size_t)bkk * N + bn + bn4;

    float acc[2][8][4];
#pragma unroll
    for (int mt = 0; mt < 2; ++mt)
#pragma unroll
        for (int nt = 0; nt < 8; ++nt)
#pragma unroll
            for (int c = 0; c < 4; ++c) acc[mt][nt][c] = 0.f;

    const int NC = K >> 5;

    auto issue = [&](int c, int stg) {
        uint32_t sA = smem_base + (uint32_t)stg * (STG_WORDS * 4);
        uint32_t sB = sA + A_WORDS * 4;
        const float* ag = Ag + c * 32;
        const float* bg = Bg + (size_t)c * 32 * N;
#pragma unroll
        for (int i = 0; i < 4; ++i)
            cp16(sA + (uint32_t)(((ar + 32 * i) * 32) + a_sw) * 4,
                 ag + (size_t)(32 * i) * K);
#pragma unroll
        for (int i = 0; i < 4; ++i)
            cp16(sB + (uint32_t)((bkk + 8 * i) * BPITCH + bn4) * 4,
                 bg + (size_t)(8 * i) * N);
    };

    issue(0, 0);
    asm volatile("cp.async.commit_group;" ::: "memory");
    if (NC > 1) issue(1, 1);
    asm volatile("cp.async.commit_group;" ::: "memory");

    for (int c = 0; c < NC; ++c) {
        asm volatile("cp.async.wait_group 1;" ::: "memory");
        __syncthreads();
        if (c + 2 < NC) issue(c + 2, (c + 2) % 3);
        asm volatile("cp.async.commit_group;" ::: "memory");

        const uint32_t* sA = smu + (c % 3) * STG_WORDS;
        const uint32_t* sB = sA + A_WORDS;
#pragma unroll
        for (int k8 = 0; k8 < 32; k8 += 8) {
            const int g0 = (k8 >> 2) ^ lm;
            const int g1 = ((k8 >> 2) + 1) ^ lm;
            uint32_t a[2][4];
#pragma unroll
            for (int mt = 0; mt < 2; ++mt) {
                int m0 = warp_m + mt * 16 + lm;
                a[mt][0] = sA[m0 * 32 + (g0 << 2) + lk];
                a[mt][1] = sA[(m0 + 8) * 32 + (g0 << 2) + lk];
                a[mt][2] = sA[m0 * 32 + (g1 << 2) + lk];
                a[mt][3] = sA[(m0 + 8) * 32 + (g1 << 2) + lk];
            }
            uint32_t b[8][2];
#pragma unroll
            for (int nt = 0; nt < 8; ++nt) {
                int n0 = warp_n + nt * 8 + lm;
                b[nt][0] = sB[(k8 + lk) * BPITCH + n0];
                b[nt][1] = sB[(k8 + 4 + lk) * BPITCH + n0];
            }
#pragma unroll
            for (int mt = 0; mt < 2; ++mt)
#pragma unroll
                for (int nt = 0; nt < 8; ++nt)
                    mma_tf32(acc[mt][nt][0], acc[mt][nt][1],
                             acc[mt][nt][2], acc[mt][nt][3],
                             a[mt][0], a[mt][1], a[mt][2], a[mt][3],
                             b[nt][0], b[nt][1]);
        }
    }

    // ---- epilogue ----
#pragma unroll
    for (int mt = 0; mt < 2; ++mt) {
        int row0 = bm + warp_m + mt * 16 + lm;
#pragma unroll
        for (int nt = 0; nt < 8; ++nt) {
            int col = bn + warp_n + nt * 8 + 2 * lk;
            float b0 = bias[col], b1 = bias[col + 1];
            float v0 = acc[mt][nt][0] + b0;
            float v1 = acc[mt][nt][1] + b1;
            float v2 = acc[mt][nt][2] + b0;
            float v3 = acc[mt][nt][3] + b1;
            if (act == 1) {
                v0 = rtf(0.5f * v0 * (1.0f + erff(v0 * 0.7071067811865476f)));
                v1 = rtf(0.5f * v1 * (1.0f + erff(v1 * 0.7071067811865476f)));
                v2 = rtf(0.5f * v2 * (1.0f + erff(v2 * 0.7071067811865476f)));
                v3 = rtf(0.5f * v3 * (1.0f + erff(v3 * 0.7071067811865476f)));
            }
            *(float2*)(C + (size_t)row0 * N + col) = make_float2(v0, v1);
            *(float2*)(C + (size_t)(row0 + 8) * N + col) = make_float2(v2, v3);
        }
    }
}

// =======================================================================
// weight preprocessing
// =======================================================================
__global__ __launch_bounds__(256) void pack_qkv_kernel(
    const float* __restrict__ Wq, const float* __restrict__ Wk,
    const float* __restrict__ Wv, const float* __restrict__ bq,
    const float* __restrict__ bk, const float* __restrict__ bv,
    float* __restrict__ Wout, float* __restrict__ bout)
{
    size_t idx = (size_t)blockIdx.x * 256 + threadIdx.x;
    const size_t TOT = (size_t)LAYERS * HID * QS;
    if (idx >= TOT) return;
    int l = (int)(idx / ((size_t)HID * QS));
    int rem = (int)(idx % ((size_t)HID * QS));
    int k = rem / QS;
    int j = rem % QS;
    const float* src = (j < HID) ? Wq : (j < 2 * HID) ? Wk : Wv;
    int jj = j % HID;
    float v = src[(size_t)l * HID * HID + (size_t)k * HID + jj];
    Wout[idx] = rtf(v);
    if (k == 0) {
        const float* bs = (j < HID) ? bq : (j < 2 * HID) ? bk : bv;
        bout[(size_t)l * QS + j] = bs[(size_t)l * HID + jj];
    }
}

__global__ __launch_bounds__(256) void round_copy_kernel(
    const float* __restrict__ src, float* __restrict__ dst, int n4)
{
    int i = blockIdx.x * 256 + threadIdx.x;
    if (i >= n4) return;
    float4 v = ((const float4*)src)[i];
    v.x = rtf(v.x); v.y = rtf(v.y); v.z = rtf(v.z); v.w = rtf(v.w);
    ((float4*)dst)[i] = v;
}

// =======================================================================
// block reduction helper (768-wide rows, 256 threads)
// =======================================================================
__device__ __forceinline__ float block_sum(float v, float* sh) {
    __syncthreads();
    int lane = threadIdx.x & 31, w = threadIdx.x >> 5;
#pragma unroll
    for (int o = 16; o; o >>= 1) v += __shfl_xor_sync(0xffffffffu, v, o);
    if (lane == 0) sh[w] = v;
    __syncthreads();
    if (w == 0) {
        float t = (lane < 8) ? sh[lane] : 0.f;
#pragma unroll
        for (int o = 4; o; o >>= 1) t += __shfl_xor_sync(0xffffffffu, t, o);
        if (lane == 0) sh[0] = t;
    }
    __syncthreads();
    return sh[0];
}

// ---------------- embeddings + LN (writes plain + rounded) ----------------
__global__ __launch_bounds__(256) void embed_ln_kernel(
    const float* __restrict__ emb, const float* __restrict__ pos,
    const float* __restrict__ tok, const float* __restrict__ g,
    const float* __restrict__ b, float* __restrict__ out,
    float* __restrict__ out_r)
{
    __shared__ float sh[8];
    int row = blockIdx.x;
    int s = row & (SS - 1);
    int tid = threadIdx.x;
    float x[3];
#pragma unroll
    for (int i = 0; i < 3; ++i) {
        int j = tid + i * 256;
        x[i] = emb[(size_t)row * HID + j] + pos[(size_t)(s + 1) * HID + j] + tok[j];
    }
    float mean = block_sum(x[0] + x[1] + x[2], sh) * (1.f / HID);
    float d2 = 0.f;
#pragma unroll
    for (int i = 0; i < 3; ++i) { float d = x[i] - mean; d2 += d * d; }
    float var = block_sum(d2, sh) * (1.f / HID);
    float rs = rsqrtf(var + 1e-12f);
#pragma unroll
    for (int i = 0; i < 3; ++i) {
        int j = tid + i * 256;
        float v = (x[i] - mean) * rs * g[j] + b[j];
        out[(size_t)row * HID + j] = v;
        out_r[(size_t)row * HID + j] = rtf(v);
    }
}

// ---------------- residual add + LN (writes plain + rounded) -------------
__global__ __launch_bounds__(256) void add_ln_kernel(
    const float* __restrict__ hin, const float* __restrict__ xin,
    const float* __restrict__ g, const float* __restrict__ b,
    float* __restrict__ out, float* __restrict__ out_r)
{
    __shared__ float sh[8];
    int row = blockIdx.x;
    int tid = threadIdx.x;
    float x[3];
#pragma unroll
    for (int i = 0; i < 3; ++i) {
        int j = tid + i * 256;
        x[i] = hin[(size_t)row * HID + j] + xin[(size_t)row * HID + j];
    }
    float mean = block_sum(x[0] + x[1] + x[2], sh) * (1.f / HID);
    float d2 = 0.f;
#pragma unroll
    for (int i = 0; i < 3; ++i) { float d = x[i] - mean; d2 += d * d; }
    float var = block_sum(d2, sh) * (1.f / HID);
    float rs = rsqrtf(var + 1e-12f);
#pragma unroll
    for (int i = 0; i < 3; ++i) {
        int j = tid + i * 256;
        float v = (x[i] - mean) * rs * g[j] + b[j];
        out[(size_t)row * HID + j] = v;
        out_r[(size_t)row * HID + j] = rtf(v);
    }
}

// ---------------- banded flash attention (reads fused QKV) ----------------
#define APITCH 68
__global__ __launch_bounds__(256) void attn_kernel(
    const float* __restrict__ QKV, const int* __restrict__ am,
    float* __restrict__ Aout)
{
    extern __shared__ float sm[];
    float* Qts = sm;
    float* Kts = sm + 64 * APITCH;
    float* Vs  = sm + 2 * 64 * APITCH;
    int*   kval = (int*)(sm + 3 * 64 * APITCH);

    int tid = threadIdx.x;
    int tx = tid & 15, ty = tid >> 4;
    int qt = blockIdx.x, h = blockIdx.y, b = blockIdx.z;
    int q0 = qt * 64;
    const size_t base2 = ((size_t)b * SS) * QS + (size_t)h * HD;
    const size_t baseO = ((size_t)b * SS) * HID + (size_t)h * HD;

    for (int idx = tid; idx < 64 * 64; idx += 256) {
        int r = idx >> 6, d = idx & 63;
        Qts[d * APITCH + r] = QKV[base2 + (size_t)(q0 + r) * QS + d] * 0.125f;
    }

    float mrow[4], lrow[4], O[4][4];
#pragma unroll
    for (int i = 0; i < 4; ++i) {
        mrow[i] = -INFINITY; lrow[i] = 0.f;
#pragma unroll
        for (int j = 0; j < 4; ++j) O[i][j] = 0.f;
    }

    for (int kt = 0; kt < 5; ++kt) {
        int ks = q0 - 128 + kt * 64;
        __syncthreads();
        for (int idx = tid; idx < 64 * 64; idx += 256) {
            int r = idx >> 6, d = idx & 63;
            int kj = ks + r;
            float kv = 0.f, vv = 0.f;
            if ((unsigned)kj < (unsigned)SS) {
                kv = QKV[base2 + (size_t)kj * QS + HID + d];
                vv = QKV[base2 + (size_t)kj * QS + 2 * HID + d];
            }
            Kts[d * APITCH + r] = kv;
            Vs[r * APITCH + d]  = vv;
        }
        if (tid < 64) {
            int kj = ks + tid;
            kval[tid] = ((unsigned)kj < (unsigned)SS) && (am[(size_t)b * SS + kj] != 0);
        }
        __syncthreads();

        float acc[4][4] = {};
#pragma unroll 8
        for (int d = 0; d < 64; ++d) {
            float4 a4 = *(const float4*)&Qts[d * APITCH + 4 * ty];
            float4 b4 = *(const float4*)&Kts[d * APITCH + 4 * tx];
            float ar[4] = {a4.x, a4.y, a4.z, a4.w};
            float br[4] = {b4.x, b4.y, b4.z, b4.w};
#pragma unroll
            for (int i = 0; i < 4; ++i)
#pragma unroll
                for (int j = 0; j < 4; ++j)
                    acc[i][j] = fmaf(ar[i], br[j], acc[i][j]);
        }
        __syncthreads();

        float p[4][4];
#pragma unroll
        for (int i = 0; i < 4; ++i) {
            int qi = q0 + ty * 4 + i;
            float rmax = -INFINITY;
#pragma unroll
            for (int j = 0; j < 4; ++j) {
                int kc = tx * 4 + j;
                int kj = ks + kc;
                bool valid = kval[kc] && (kj >= qi - WIN) && (kj <= qi + WIN);
                float sc = valid ? acc[i][j] : -1e9f;
                acc[i][j] = sc;
                rmax = fmaxf(rmax, sc);
            }
#pragma unroll
            for (int o = 8; o; o >>= 1)
                rmax = fmaxf(rmax, __shfl_xor_sync(0xffffffffu, rmax, o, 16));
            float mnew = fmaxf(mrow[i], rmax);
            float scal = __expf(mrow[i] - mnew);
            mrow[i] = mnew;
            float ls = 0.f;
#pragma unroll
            for (int j = 0; j < 4; ++j) {
                float pv = __expf(acc[i][j] - mnew);
                p[i][j] = pv;
                ls += pv;
            }
#pragma unroll
            for (int o = 8; o; o >>= 1)
                ls += __shfl_xor_sync(0xffffffffu, ls, o, 16);
            lrow[i] = lrow[i] * scal + ls;
#pragma unroll
            for (int j = 0; j < 4; ++j) {
                O[i][j] *= scal;
                Kts[(tx * 4 + j) * APITCH + ty * 4 + i] = p[i][j];
            }
        }
        __syncthreads();

#pragma unroll 8
        for (int k = 0; k < 64; ++k) {
            float4 p4 = *(const float4*)&Kts[k * APITCH + 4 * ty];
            float4 v4 = *(const float4*)&Vs[k * APITCH + 4 * tx];
            float pr[4] = {p4.x, p4.y, p4.z, p4.w};
            float vr[4] = {v4.x, v4.y, v4.z, v4.w};
#pragma unroll
            for (int i = 0; i < 4; ++i)
#pragma unroll
                for (int j = 0; j < 4; ++j)
                    O[i][j] = fmaf(pr[i], vr[j], O[i][j]);
        }
    }

#pragma unroll
    for (int i = 0; i < 4; ++i) {
        float rl = (lrow[i] > 0.f) ? (1.f / lrow[i]) : 0.f;
#pragma unroll
        for (int j = 0; j < 4; ++j)
            Aout[baseO + (size_t)(q0 + ty * 4 + i) * HID + tx * 4 + j]
                = rtf(O[i][j] * rl);
    }
}

// ---------------- final projection + sigmoid ----------------
__global__ __launch_bounds__(256) void final_kernel(
    const float* __restrict__ h, const float* __restrict__ Wp,
    const float* __restrict__ bp, float* __restrict__ out)
{
    int gtid = blockIdx.x * 256 + threadIdx.x;
    int row = gtid >> 5;
    int lane = gtid & 31;
    if (row >= MROWS) return;
    float s = 0.f;
    for (int k = lane; k < HID; k += 32)
        s = fmaf(h[(size_t)row * HID + k], Wp[k], s);
#pragma unroll
    for (int o = 16; o; o >>= 1) s += __shfl_xor_sync(0xffffffffu, s, o);
    if (lane == 0)
        out[row] = 1.f / (1.f + expf(-(s + bp[0])));
}

// ---------------- host orchestration ----------------
extern "C" void kernel_launch(void* const* d_in, const int* in_sizes, int n_in,
                              void* d_out, int out_size)
{
    const float* emb     = (const float*)d_in[0];
    const int*   amask   = (const int*)  d_in[1];
    const float* pos     = (const float*)d_in[2];
    const float* tok     = (const float*)d_in[3];
    const float* eln_g   = (const float*)d_in[4];
    const float* eln_b   = (const float*)d_in[5];
    const float* Wq      = (const float*)d_in[6];
    const float* bq      = (const float*)d_in[7];
    const float* Wk      = (const float*)d_in[8];
    const float* bk      = (const float*)d_in[9];
    const float* Wv      = (const float*)d_in[10];
    const float* bv      = (const float*)d_in[11];
    const float* Wo      = (const float*)d_in[12];
    const float* bo      = (const float*)d_in[13];
    const float* ln1_g   = (const float*)d_in[14];
    const float* ln1_b   = (const float*)d_in[15];
    const float* Wi      = (const float*)d_in[16];
    const float* bi      = (const float*)d_in[17];
    const float* Wf      = (const float*)d_in[18];
    const float* bf      = (const float*)d_in[19];
    const float* ln2_g   = (const float*)d_in[20];
    const float* ln2_b   = (const float*)d_in[21];
    const float* Wp      = (const float*)d_in[22];
    const float* bp      = (const float*)d_in[23];

    float *h_, *hr_, *qkv_, *a_, *t_, *f_;
    float *wqkv_, *bqkv_, *wo_, *wi_, *wf_;
    cudaGetSymbolAddress((void**)&h_,  g_h);
    cudaGetSymbolAddress((void**)&hr_, g_hr);
    cudaGetSymbolAddress((void**)&qkv_, g_qkv);
    cudaGetSymbolAddress((void**)&a_,  g_a);
    cudaGetSymbolAddress((void**)&t_,  g_t);
    cudaGetSymbolAddress((void**)&f_,  g_f);
    cudaGetSymbolAddress((void**)&wqkv_, g_wqkv);
    cudaGetSymbolAddress((void**)&bqkv_, g_bqkv);
    cudaGetSymbolAddress((void**)&wo_, g_wo);
    cudaGetSymbolAddress((void**)&wi_, g_wi);
    cudaGetSymbolAddress((void**)&wf_, g_wf);

    const int attn_smem = (3 * 64 * APITCH) * 4 + 64 * 4;  // 52480 B
    cudaFuncSetAttribute(attn_kernel,
                         cudaFuncAttributeMaxDynamicSharedMemorySize, attn_smem);
    cudaFuncSetAttribute(gemm_tc_kernel,
                         cudaFuncAttributeMaxDynamicSharedMemorySize, GEMM_SMEM_BYTES);

    // ---- weight preprocessing (tf32 rounding, QKV pack) ----
    {
        size_t tot = (size_t)LAYERS * HID * QS;
        pack_qkv_kernel<<<(unsigned)((tot + 255) / 256), 256>>>(
            Wq, Wk, Wv, bq, bk, bv, wqkv_, bqkv_);
        int n4o = LAYERS * HID * HID / 4;
        round_copy_kernel<<<(n4o + 255) / 256, 256>>>(Wo, wo_, n4o);
        int n4i = LAYERS * HID * 4 * HID / 4;
        round_copy_kernel<<<(n4i + 255) / 256, 256>>>(Wi, wi_, n4i);
        round_copy_kernel<<<(n4i + 255) / 256, 256>>>(Wf, wf_, n4i);
    }

    embed_ln_kernel<<<MROWS, 256>>>(emb, pos, tok, eln_g, eln_b, h_, hr_);

    const size_t WSQ = (size_t)HID * HID;
    const size_t WSI = (size_t)HID * 4 * HID;
    const size_t WSQKV = (size_t)HID * QS;

    for (int l = 0; l < LAYERS; ++l) {
        dim3 gqkv(QS / 128, MROWS / 128);         // (18, 64)
        gemm_tc_kernel<<<gqkv, 256, GEMM_SMEM_BYTES>>>(
            hr_, wqkv_ + l * WSQKV, bqkv_ + (size_t)l * QS, qkv_,
            MROWS, QS, HID, 0);

        dim3 ga(SS / 64, HEADS, BB);
        attn_kernel<<<ga, 256, attn_smem>>>(qkv_, amask, a_);

        dim3 g1(HID / 128, MROWS / 128);          // (6, 64)
        gemm_tc_kernel<<<g1, 256, GEMM_SMEM_BYTES>>>(
            a_, wo_ + l * WSQ, bo + (size_t)l * HID, t_, MROWS, HID, HID, 0);
        add_ln_kernel<<<MROWS, 256>>>(h_, t_, ln1_g + l * HID, ln1_b + l * HID, h_, hr_);

        dim3 g2(4 * HID / 128, MROWS / 128);      // (24, 64)
        gemm_tc_kernel<<<g2, 256, GEMM_SMEM_BYTES>>>(
            hr_, wi_ + l * WSI, bi + (size_t)l * 4 * HID, f_,
            MROWS, 4 * HID, HID, 1);
        gemm_tc_kernel<<<g1, 256, GEMM_SMEM_BYTES>>>(
            f_, wf_ + l * WSI, bf + (size_t)l * HID, t_, MROWS, HID, 4 * HID, 0);
        add_ln_kernel<<<MROWS, 256>>>(h_, t_, ln2_g + l * HID, ln2_b + l * HID, h_, hr_);
    }

    final_kernel<<<(MROWS * 32 + 255) / 256, 256>>>(h_, Wp, bp, (float*)d_out);
}

// round 7
// speedup vs baseline: 4.9458x; 1.3872x over previous
#include <cuda_runtime.h>
#include <cuda_fp16.h>
#include <math.h>
#include <stdint.h>

// ---------------- problem constants ----------------
#define BB      2
#define SS      4096
#define HID     768
#define LAYERS  4
#define HEADS   12
#define HD      64
#define WIN     128          // one-sided window
#define MROWS   (BB*SS)      // 8192 token rows
#define QS      2304         // fused QKV row stride

// ---------------- scratch (device globals; no allocation) ----------------
__device__ __align__(256) float  g_h  [MROWS * HID];
__device__ __align__(256) __half g_hb [MROWS * HID];        // half copy of h
__device__ __align__(256) float  g_qkv[MROWS * QS];
__device__ __align__(256) __half g_ab [MROWS * HID];        // attention out (half)
__device__ __align__(256) float  g_t  [MROWS * HID];
__device__ __align__(256) __half g_fb [MROWS * 4 * HID];    // GELU out (half)
// preprocessed weights: transposed to [N][K], half
__device__ __align__(256) __half g_wqkv[LAYERS * QS * HID];
__device__ __align__(256) float  g_bqkv[LAYERS * QS];
__device__ __align__(256) __half g_wo [LAYERS * HID * HID];
__device__ __align__(256) __half g_wi [LAYERS * 4 * HID * HID];
__device__ __align__(256) __half g_wf [LAYERS * HID * 4 * HID];

// =======================================================================
// helpers
// =======================================================================
__device__ __forceinline__ void mma_f16(
    float& d0, float& d1, float& d2, float& d3,
    uint32_t a0, uint32_t a1, uint32_t a2, uint32_t a3,
    uint32_t b0, uint32_t b1)
{
    asm volatile(
        "mma.sync.aligned.m16n8k16.row.col.f32.f16.f16.f32 "
        "{%0,%1,%2,%3}, {%4,%5,%6,%7}, {%8,%9}, {%0,%1,%2,%3};"
        : "+f"(d0), "+f"(d1), "+f"(d2), "+f"(d3)
        : "r"(a0), "r"(a1), "r"(a2), "r"(a3), "r"(b0), "r"(b1));
}
__device__ __forceinline__ void cp16(uint32_t dst, const void* src) {
    asm volatile("cp.async.cg.shared.global [%0], [%1], 16;"
                 :: "r"(dst), "l"(src));
}

// =======================================================================
// fp16 mma.sync GEMM, cp.async 3-stage pipeline.
// C[M,N] = A[M,K]*W[N,K]^T + bias.  act=0 -> fp32 C; act=1 -> GELU, half C.
// A: [M,K] half (row-major). W: [N,K] half (row-major, i.e. pre-transposed).
// block 128x128, BK=32, 256 threads (8 warps), warp tile 32x64.
// smem tiles A,B both [128][32] half with quad swizzle phys=q^((r>>1)&3).
// =======================================================================
#define TILE_BYTES (128*64)              // 8 KB per operand tile
#define STG_BYTES  (2*TILE_BYTES)        // 16 KB per stage
#define GEMM_SMEM_BYTES (3*STG_BYTES)    // 48 KB

__global__ __launch_bounds__(256, 2) void gemm_f16_kernel(
    const __half* __restrict__ A, const __half* __restrict__ Bw,
    const float* __restrict__ bias, void* __restrict__ Cout,
    int M, int N, int K, int act)
{
    extern __shared__ uint32_t smu[];
    uint32_t smem_base = (uint32_t)__cvta_generic_to_shared(smu);

    const int tid  = threadIdx.x;
    const int lane = tid & 31;
    const int wid  = tid >> 5;
    const int lm   = lane >> 2;        // 0..7
    const int lk   = lane & 3;         // 0..3
    const int warp_m = (wid >> 1) * 32;
    const int warp_n = (wid & 1) * 64;
    const int bm = blockIdx.y * 128;
    const int bn = blockIdx.x * 128;

    const __half* Ag = A  + (size_t)bm * K;
    const __half* Bg = Bw + (size_t)bn * K;

    // chunk mapping for cp.async (each thread: chunks tid and tid+256)
    const int r0 = tid >> 2, q0c = tid & 3;
    const int r1 = (tid + 256) >> 2, q1c = tid & 3;   // +256 keeps q, r += 64
    const uint32_t offA0 = (uint32_t)(r0 * 64 + (q0c ^ ((r0 >> 1) & 3)) * 16);
    const uint32_t offA1 = (uint32_t)(r1 * 64 + (q1c ^ ((r1 >> 1) & 3)) * 16);

    float acc[2][8][4];
#pragma unroll
    for (int mt = 0; mt < 2; ++mt)
#pragma unroll
        for (int nt = 0; nt < 8; ++nt)
#pragma unroll
            for (int c = 0; c < 4; ++c) acc[mt][nt][c] = 0.f;

    const int NC = K >> 5;

    auto issue = [&](int c, int stg) {
        uint32_t sA = smem_base + (uint32_t)stg * STG_BYTES;
        uint32_t sB = sA + TILE_BYTES;
        const __half* ag = Ag + c * 32;
        const __half* bg = Bg + c * 32;
        cp16(sA + offA0, ag + (size_t)r0 * K + q0c * 8);
        cp16(sA + offA1, ag + (size_t)r1 * K + q1c * 8);
        cp16(sB + offA0, bg + (size_t)r0 * K + q0c * 8);
        cp16(sB + offA1, bg + (size_t)r1 * K + q1c * 8);
    };

    issue(0, 0);
    asm volatile("cp.async.commit_group;" ::: "memory");
    if (NC > 1) issue(1, 1);
    asm volatile("cp.async.commit_group;" ::: "memory");

    const int swz = (lm >> 1) & 3;   // row-dependent quad XOR (warp-uniform per lm)

    for (int c = 0; c < NC; ++c) {
        asm volatile("cp.async.wait_group 1;" ::: "memory");
        __syncthreads();
        if (c + 2 < NC) issue(c + 2, (c + 2) % 3);
        asm volatile("cp.async.commit_group;" ::: "memory");

        const uint32_t* sA = smu + (c % 3) * (STG_BYTES / 4);
        const uint32_t* sB = sA + TILE_BYTES / 4;
#pragma unroll
        for (int s = 0; s < 2; ++s) {            // two k16 steps per BK=32
            const int q0 = 2 * s;
            const int pq0 = (q0 ^ swz) * 4 + lk;
            const int pq1 = ((q0 + 1) ^ swz) * 4 + lk;
            uint32_t a[2][4];
#pragma unroll
            for (int mt = 0; mt < 2; ++mt) {
                int m0 = warp_m + mt * 16 + lm;
                a[mt][0] = sA[m0 * 16 + pq0];
                a[mt][1] = sA[(m0 + 8) * 16 + pq0];
                a[mt][2] = sA[m0 * 16 + pq1];
                a[mt][3] = sA[(m0 + 8) * 16 + pq1];
            }
            uint32_t b[8][2];
#pragma unroll
            for (int nt = 0; nt < 8; ++nt) {
                int n0 = warp_n + nt * 8 + lm;
                b[nt][0] = sB[n0 * 16 + pq0];
                b[nt][1] = sB[n0 * 16 + pq1];
            }
#pragma unroll
            for (int mt = 0; mt < 2; ++mt)
#pragma unroll
                for (int nt = 0; nt < 8; ++nt)
                    mma_f16(acc[mt][nt][0], acc[mt][nt][1],
                            acc[mt][nt][2], acc[mt][nt][3],
                            a[mt][0], a[mt][1], a[mt][2], a[mt][3],
                            b[nt][0], b[nt][1]);
        }
    }

    // ---- epilogue ----
#pragma unroll
    for (int mt = 0; mt < 2; ++mt) {
        int row0 = bm + warp_m + mt * 16 + lm;
#pragma unroll
        for (int nt = 0; nt < 8; ++nt) {
            int col = bn + warp_n + nt * 8 + 2 * lk;
            float b0 = bias[col], b1 = bias[col + 1];
            float v0 = acc[mt][nt][0] + b0;
            float v1 = acc[mt][nt][1] + b1;
            float v2 = acc[mt][nt][2] + b0;
            float v3 = acc[mt][nt][3] + b1;
            if (act == 1) {
                v0 = 0.5f * v0 * (1.0f + erff(v0 * 0.7071067811865476f));
                v1 = 0.5f * v1 * (1.0f + erff(v1 * 0.7071067811865476f));
                v2 = 0.5f * v2 * (1.0f + erff(v2 * 0.7071067811865476f));
                v3 = 0.5f * v3 * (1.0f + erff(v3 * 0.7071067811865476f));
                __half* C = (__half*)Cout;
                *(__half2*)(C + (size_t)row0 * N + col) = __floats2half2_rn(v0, v1);
                *(__half2*)(C + (size_t)(row0 + 8) * N + col) = __floats2half2_rn(v2, v3);
            } else {
                float* C = (float*)Cout;
                *(float2*)(C + (size_t)row0 * N + col) = make_float2(v0, v1);
                *(float2*)(C + (size_t)(row0 + 8) * N + col) = make_float2(v2, v3);
            }
        }
    }
}

// =======================================================================
// weight preprocessing: transpose fp32 [K,N] -> half [N,K]
// =======================================================================
__global__ __launch_bounds__(256) void transpose_h_kernel(
    const float* __restrict__ src, __half* __restrict__ dst, int K, int N)
{
    __shared__ float t[32][33];
    int tx = threadIdx.x, ty = threadIdx.y;      // block (32,8)
    int x = blockIdx.x * 32 + tx;                // n
    int y0 = blockIdx.y * 32;                    // k
#pragma unroll
    for (int j = 0; j < 32; j += 8)
        t[ty + j][tx] = src[(size_t)(y0 + ty + j) * N + x];
    __syncthreads();
    int n_out = blockIdx.x * 32 + ty;
#pragma unroll
    for (int j = 0; j < 32; j += 8)
        dst[(size_t)(n_out + j) * K + y0 + tx] = __float2half_rn(t[tx][ty + j]);
}

__global__ __launch_bounds__(256) void bias_qkv_kernel(
    const float* __restrict__ bq, const float* __restrict__ bk,
    const float* __restrict__ bv, float* __restrict__ bout)
{
    int idx = blockIdx.x * 256 + threadIdx.x;
    if (idx >= LAYERS * QS) return;
    int l = idx / QS, j = idx % QS;
    const float* src = (j < HID) ? bq : (j < 2 * HID) ? bk : bv;
    bout[idx] = src[(size_t)l * HID + (j % HID)];
}

// =======================================================================
// block reduction helper (768-wide rows, 256 threads)
// =======================================================================
__device__ __forceinline__ float block_sum(float v, float* sh) {
    __syncthreads();
    int lane = threadIdx.x & 31, w = threadIdx.x >> 5;
#pragma unroll
    for (int o = 16; o; o >>= 1) v += __shfl_xor_sync(0xffffffffu, v, o);
    if (lane == 0) sh[w] = v;
    __syncthreads();
    if (w == 0) {
        float t = (lane < 8) ? sh[lane] : 0.f;
#pragma unroll
        for (int o = 4; o; o >>= 1) t += __shfl_xor_sync(0xffffffffu, t, o);
        if (lane == 0) sh[0] = t;
    }
    __syncthreads();
    return sh[0];
}

// ---------------- embeddings + LN (writes fp32 + half) ----------------
__global__ __launch_bounds__(256) void embed_ln_kernel(
    const float* __restrict__ emb, const float* __restrict__ pos,
    const float* __restrict__ tok, const float* __restrict__ g,
    const float* __restrict__ b, float* __restrict__ out,
    __half* __restrict__ out_h)
{
    __shared__ float sh[8];
    int row = blockIdx.x;
    int s = row & (SS - 1);
    int tid = threadIdx.x;
    float x[3];
#pragma unroll
    for (int i = 0; i < 3; ++i) {
        int j = tid + i * 256;
        x[i] = emb[(size_t)row * HID + j] + pos[(size_t)(s + 1) * HID + j] + tok[j];
    }
    float mean = block_sum(x[0] + x[1] + x[2], sh) * (1.f / HID);
    float d2 = 0.f;
#pragma unroll
    for (int i = 0; i < 3; ++i) { float d = x[i] - mean; d2 += d * d; }
    float var = block_sum(d2, sh) * (1.f / HID);
    float rs = rsqrtf(var + 1e-12f);
#pragma unroll
    for (int i = 0; i < 3; ++i) {
        int j = tid + i * 256;
        float v = (x[i] - mean) * rs * g[j] + b[j];
        out[(size_t)row * HID + j] = v;
        out_h[(size_t)row * HID + j] = __float2half_rn(v);
    }
}

// ---------------- residual add + LN (writes fp32 + half) -------------
__global__ __launch_bounds__(256) void add_ln_kernel(
    const float* __restrict__ hin, const float* __restrict__ xin,
    const float* __restrict__ g, const float* __restrict__ b,
    float* __restrict__ out, __half* __restrict__ out_h)
{
    __shared__ float sh[8];
    int row = blockIdx.x;
    int tid = threadIdx.x;
    float x[3];
#pragma unroll
    for (int i = 0; i < 3; ++i) {
        int j = tid + i * 256;
        x[i] = hin[(size_t)row * HID + j] + xin[(size_t)row * HID + j];
    }
    float mean = block_sum(x[0] + x[1] + x[2], sh) * (1.f / HID);
    float d2 = 0.f;
#pragma unroll
    for (int i = 0; i < 3; ++i) { float d = x[i] - mean; d2 += d * d; }
    float var = block_sum(d2, sh) * (1.f / HID);
    float rs = rsqrtf(var + 1e-12f);
#pragma unroll
    for (int i = 0; i < 3; ++i) {
        int j = tid + i * 256;
        float v = (x[i] - mean) * rs * g[j] + b[j];
        out[(size_t)row * HID + j] = v;
        out_h[(size_t)row * HID + j] = __float2half_rn(v);
    }
}

// ---------------- banded flash attention (fused QKV in, half out) --------
#define APITCH 68
__global__ __launch_bounds__(256) void attn_kernel(
    const float* __restrict__ QKV, const int* __restrict__ am,
    __half* __restrict__ Aout)
{
    extern __shared__ float sm[];
    float* Qts = sm;
    float* Kts = sm + 64 * APITCH;
    float* Vs  = sm + 2 * 64 * APITCH;
    int*   kval = (int*)(sm + 3 * 64 * APITCH);

    int tid = threadIdx.x;
    int tx = tid & 15, ty = tid >> 4;
    int qt = blockIdx.x, h = blockIdx.y, b = blockIdx.z;
    int q0 = qt * 64;
    const size_t base2 = ((size_t)b * SS) * QS + (size_t)h * HD;
    const size_t baseO = ((size_t)b * SS) * HID + (size_t)h * HD;

    for (int idx = tid; idx < 64 * 64; idx += 256) {
        int r = idx >> 6, d = idx & 63;
        Qts[d * APITCH + r] = QKV[base2 + (size_t)(q0 + r) * QS + d] * 0.125f;
    }

    float mrow[4], lrow[4], O[4][4];
#pragma unroll
    for (int i = 0; i < 4; ++i) {
        mrow[i] = -INFINITY; lrow[i] = 0.f;
#pragma unroll
        for (int j = 0; j < 4; ++j) O[i][j] = 0.f;
    }

    for (int kt = 0; kt < 5; ++kt) {
        int ks = q0 - 128 + kt * 64;
        __syncthreads();
        for (int idx = tid; idx < 64 * 64; idx += 256) {
            int r = idx >> 6, d = idx & 63;
            int kj = ks + r;
            float kv = 0.f, vv = 0.f;
            if ((unsigned)kj < (unsigned)SS) {
                kv = QKV[base2 + (size_t)kj * QS + HID + d];
                vv = QKV[base2 + (size_t)kj * QS + 2 * HID + d];
            }
            Kts[d * APITCH + r] = kv;
            Vs[r * APITCH + d]  = vv;
        }
        if (tid < 64) {
            int kj = ks + tid;
            kval[tid] = ((unsigned)kj < (unsigned)SS) && (am[(size_t)b * SS + kj] != 0);
        }
        __syncthreads();

        float acc[4][4] = {};
#pragma unroll 8
        for (int d = 0; d < 64; ++d) {
            float4 a4 = *(const float4*)&Qts[d * APITCH + 4 * ty];
            float4 b4 = *(const float4*)&Kts[d * APITCH + 4 * tx];
            float ar[4] = {a4.x, a4.y, a4.z, a4.w};
            float br[4] = {b4.x, b4.y, b4.z, b4.w};
#pragma unroll
            for (int i = 0; i < 4; ++i)
#pragma unroll
                for (int j = 0; j < 4; ++j)
                    acc[i][j] = fmaf(ar[i], br[j], acc[i][j]);
        }
        __syncthreads();

        float p[4][4];
#pragma unroll
        for (int i = 0; i < 4; ++i) {
            int qi = q0 + ty * 4 + i;
            float rmax = -INFINITY;
#pragma unroll
            for (int j = 0; j < 4; ++j) {
                int kc = tx * 4 + j;
                int kj = ks + kc;
                bool valid = kval[kc] && (kj >= qi - WIN) && (kj <= qi + WIN);
                float sc = valid ? acc[i][j] : -1e9f;
                acc[i][j] = sc;
                rmax = fmaxf(rmax, sc);
            }
#pragma unroll
            for (int o = 8; o; o >>= 1)
                rmax = fmaxf(rmax, __shfl_xor_sync(0xffffffffu, rmax, o, 16));
            float mnew = fmaxf(mrow[i], rmax);
            float scal = __expf(mrow[i] - mnew);
            mrow[i] = mnew;
            float ls = 0.f;
#pragma unroll
            for (int j = 0; j < 4; ++j) {
                float pv = __expf(acc[i][j] - mnew);
                p[i][j] = pv;
                ls += pv;
            }
#pragma unroll
            for (int o = 8; o; o >>= 1)
                ls += __shfl_xor_sync(0xffffffffu, ls, o, 16);
            lrow[i] = lrow[i] * scal + ls;
#pragma unroll
            for (int j = 0; j < 4; ++j) {
                O[i][j] *= scal;
                Kts[(tx * 4 + j) * APITCH + ty * 4 + i] = p[i][j];
            }
        }
        __syncthreads();

#pragma unroll 8
        for (int k = 0; k < 64; ++k) {
            float4 p4 = *(const float4*)&Kts[k * APITCH + 4 * ty];
            float4 v4 = *(const float4*)&Vs[k * APITCH + 4 * tx];
            float pr[4] = {p4.x, p4.y, p4.z, p4.w};
            float vr[4] = {v4.x, v4.y, v4.z, v4.w};
#pragma unroll
            for (int i = 0; i < 4; ++i)
#pragma unroll
                for (int j = 0; j < 4; ++j)
                    O[i][j] = fmaf(pr[i], vr[j], O[i][j]);
        }
    }

#pragma unroll
    for (int i = 0; i < 4; ++i) {
        float rl = (lrow[i] > 0.f) ? (1.f / lrow[i]) : 0.f;
#pragma unroll
        for (int j = 0; j < 4; ++j)
            Aout[baseO + (size_t)(q0 + ty * 4 + i) * HID + tx * 4 + j]
                = __float2half_rn(O[i][j] * rl);
    }
}

// ---------------- final projection + sigmoid ----------------
__global__ __launch_bounds__(256) void final_kernel(
    const float* __restrict__ h, const float* __restrict__ Wp,
    const float* __restrict__ bp, float* __restrict__ out)
{
    int gtid = blockIdx.x * 256 + threadIdx.x;
    int row = gtid >> 5;
    int lane = gtid & 31;
    if (row >= MROWS) return;
    float s = 0.f;
    for (int k = lane; k < HID; k += 32)
        s = fmaf(h[(size_t)row * HID + k], Wp[k], s);
#pragma unroll
    for (int o = 16; o; o >>= 1) s += __shfl_xor_sync(0xffffffffu, s, o);
    if (lane == 0)
        out[row] = 1.f / (1.f + expf(-(s + bp[0])));
}

// ---------------- host orchestration ----------------
extern "C" void kernel_launch(void* const* d_in, const int* in_sizes, int n_in,
                              void* d_out, int out_size)
{
    const float* emb     = (const float*)d_in[0];
    const int*   amask   = (const int*)  d_in[1];
    const float* pos     = (const float*)d_in[2];
    const float* tok     = (const float*)d_in[3];
    const float* eln_g   = (const float*)d_in[4];
    const float* eln_b   = (const float*)d_in[5];
    const float* Wq      = (const float*)d_in[6];
    const float* bq      = (const float*)d_in[7];
    const float* Wk      = (const float*)d_in[8];
    const float* bk      = (const float*)d_in[9];
    const float* Wv      = (const float*)d_in[10];
    const float* bv      = (const float*)d_in[11];
    const float* Wo      = (const float*)d_in[12];
    const float* bo      = (const float*)d_in[13];
    const float* ln1_g   = (const float*)d_in[14];
    const float* ln1_b   = (const float*)d_in[15];
    const float* Wi      = (const float*)d_in[16];
    const float* bi      = (const float*)d_in[17];
    const float* Wf      = (const float*)d_in[18];
    const float* bf      = (const float*)d_in[19];
    const float* ln2_g   = (const float*)d_in[20];
    const float* ln2_b   = (const float*)d_in[21];
    const float* Wp      = (const float*)d_in[22];
    const float* bp      = (const float*)d_in[23];

    float  *h_, *qkv_, *t_, *bqkv_;
    __half *hb_, *ab_, *fb_, *wqkv_, *wo_, *wi_, *wf_;
    cudaGetSymbolAddress((void**)&h_,   g_h);
    cudaGetSymbolAddress((void**)&hb_,  g_hb);
    cudaGetSymbolAddress((void**)&qkv_, g_qkv);
    cudaGetSymbolAddress((void**)&ab_,  g_ab);
    cudaGetSymbolAddress((void**)&t_,   g_t);
    cudaGetSymbolAddress((void**)&fb_,  g_fb);
    cudaGetSymbolAddress((void**)&wqkv_, g_wqkv);
    cudaGetSymbolAddress((void**)&bqkv_, g_bqkv);
    cudaGetSymbolAddress((void**)&wo_,  g_wo);
    cudaGetSymbolAddress((void**)&wi_,  g_wi);
    cudaGetSymbolAddress((void**)&wf_,  g_wf);

    const int attn_smem = (3 * 64 * APITCH) * 4 + 64 * 4;  // 52480 B
    cudaFuncSetAttribute(attn_kernel,
                         cudaFuncAttributeMaxDynamicSharedMemorySize, attn_smem);
    cudaFuncSetAttribute(gemm_f16_kernel,
                         cudaFuncAttributeMaxDynamicSharedMemorySize, GEMM_SMEM_BYTES);

    const size_t WSQ   = (size_t)HID * HID;
    const size_t WSI   = (size_t)HID * 4 * HID;
    const size_t WSQKV = (size_t)QS * HID;

    // ---- weight preprocessing: transpose + fp16 round ----
    {
        dim3 blk(32, 8);
        for (int l = 0; l < LAYERS; ++l) {
            dim3 gsq(HID / 32, HID / 32);
            transpose_h_kernel<<<gsq, blk>>>(Wq + l * WSQ, wqkv_ + l * WSQKV, HID, HID);
            transpose_h_kernel<<<gsq, blk>>>(Wk + l * WSQ, wqkv_ + l * WSQKV + (size_t)HID * HID, HID, HID);
            transpose_h_kernel<<<gsq, blk>>>(Wv + l * WSQ, wqkv_ + l * WSQKV + (size_t)2 * HID * HID, HID, HID);
            transpose_h_kernel<<<gsq, blk>>>(Wo + l * WSQ, wo_ + l * WSQ, HID, HID);
            dim3 gi(4 * HID / 32, HID / 32);
            transpose_h_kernel<<<gi, blk>>>(Wi + l * WSI, wi_ + l * WSI, HID, 4 * HID);
            dim3 gf(HID / 32, 4 * HID / 32);
            transpose_h_kernel<<<gf, blk>>>(Wf + l * WSI, wf_ + l * WSI, 4 * HID, HID);
        }
        bias_qkv_kernel<<<(LAYERS * QS + 255) / 256, 256>>>(bq, bk, bv, bqkv_);
    }

    embed_ln_kernel<<<MROWS, 256>>>(emb, pos, tok, eln_g, eln_b, h_, hb_);

    for (int l = 0; l < LAYERS; ++l) {
        dim3 gqkv(QS / 128, MROWS / 128);         // (18, 64)
        gemm_f16_kernel<<<gqkv, 256, GEMM_SMEM_BYTES>>>(
            hb_, wqkv_ + l * WSQKV, bqkv_ + (size_t)l * QS, qkv_,
            MROWS, QS, HID, 0);

        dim3 ga(SS / 64, HEADS, BB);
        attn_kernel<<<ga, 256, attn_smem>>>(qkv_, amask, ab_);

        dim3 g1(HID / 128, MROWS / 128);          // (6, 64)
        gemm_f16_kernel<<<g1, 256, GEMM_SMEM_BYTES>>>(
            ab_, wo_ + l * WSQ, bo + (size_t)l * HID, t_, MROWS, HID, HID, 0);
        add_ln_kernel<<<MROWS, 256>>>(h_, t_, ln1_g + l * HID, ln1_b + l * HID, h_, hb_);

        dim3 g2(4 * HID / 128, MROWS / 128);      // (24, 64)
        gemm_f16_kernel<<<g2, 256, GEMM_SMEM_BYTES>>>(
            hb_, wi_ + l * WSI, bi + (size_t)l * 4 * HID, fb_,
            MROWS, 4 * HID, HID, 1);
        gemm_f16_kernel<<<g1, 256, GEMM_SMEM_BYTES>>>(
            fb_, wf_ + l * WSI, bf + (size_t)l * HID, t_, MROWS, HID, 4 * HID, 0);
        add_ln_kernel<<<MROWS, 256>>>(h_, t_, ln2_g + l * HID, ln2_b + l * HID, h_, hb_);
    }

    final_kernel<<<(MROWS * 32 + 255) / 256, 256>>>(h_, Wp, bp, (float*)d_out);
}